// round 7
// baseline (speedup 1.0000x reference)
#include <cuda_runtime.h>
#include <cuda_fp16.h>
#include <cstddef>
#include <cstdint>

#define BB 64
#define PP 2000
#define DD 128
#define TT 200
#define EPSL 1e-5f

// ---------------- scratch ----------------
__device__ float g_tour [BB * TT * DD];
__device__ float g_tb   [BB * TT * DD];
__device__ float g_added[BB * PP * DD];
__device__ float g_sum  [BB * DD];
__device__ float g_sumsq[BB * DD];
// fp16x2 packed weights: [n][kp], kp in [0,64), pair = (W[2kp][n], W[2kp+1][n])
__device__ unsigned g_W1p[DD * 64];   // W1 rows [0,128)
__device__ unsigned g_Wbp[DD * 64];   // W1 rows [128,256)
__device__ unsigned g_W2p[DD * 64];

static __device__ __forceinline__ unsigned pack2(float v0, float v1) {
    __half2 h = __floats2half2_rn(v0, v1);
    return *reinterpret_cast<unsigned*>(&h);
}

static __device__ __forceinline__ void mma16816(float* c, unsigned a0, unsigned a1,
                                                unsigned a2, unsigned a3,
                                                unsigned b0, unsigned b1) {
    asm volatile(
        "mma.sync.aligned.m16n8k16.row.col.f32.f16.f16.f32 "
        "{%0,%1,%2,%3}, {%4,%5,%6,%7}, {%8,%9}, {%0,%1,%2,%3};"
        : "+f"(c[0]), "+f"(c[1]), "+f"(c[2]), "+f"(c[3])
        : "r"(a0), "r"(a1), "r"(a2), "r"(a3), "r"(b0), "r"(b1));
}

#define LDSM4(r0, r1, r2, r3, a) \
    asm volatile("ldmatrix.sync.aligned.m8n8.x4.shared.b16 {%0,%1,%2,%3}, [%4];" \
                 : "=r"(r0), "=r"(r1), "=r"(r2), "=r"(r3) : "r"(a))

static __device__ __forceinline__ uint32_t smem_u32(const void* p) {
    uint32_t a;
    asm("{ .reg .u64 t; cvta.to.shared.u64 t, %1; cvt.u32.u64 %0, t; }" : "=r"(a) : "l"(p));
    return a;
}

// ---------------- K0: zero + pack weights (merged) ----------------
__global__ void k_init(const float* __restrict__ W1, const float* __restrict__ W2) {
    int i = blockIdx.x * blockDim.x + threadIdx.x;
    if (i < BB * TT * DD) g_tour[i] = 0.f;
    if (i < BB * DD) { g_sum[i] = 0.f; g_sumsq[i] = 0.f; }
    if (i < 3 * DD * 64) {
        int m  = i >> 13;
        int n  = (i >> 6) & 127;
        int kp = i & 63;
        const float* W = (m == 0) ? W1 : (m == 1) ? (W1 + 128 * DD) : W2;
        unsigned p = pack2(W[(2 * kp) * DD + n], W[(2 * kp + 1) * DD + n]);
        if (m == 0)      g_W1p[n * 64 + kp] = p;
        else if (m == 1) g_Wbp[n * 64 + kp] = p;
        else             g_W2p[n * 64 + kp] = p;
    }
}

// ---------------- K1: segment sum (vector global atomics) ----------------
__global__ void k_seg(const float* __restrict__ emb, const int* __restrict__ tidx) {
    int i = blockIdx.x * blockDim.x + threadIdx.x;
    int d4 = i & 31;
    int r  = i >> 5;
    if (r >= BB * PP) return;
    int b = r / PP, p = r - b * PP;
    const float4 v = *reinterpret_cast<const float4*>(emb + (size_t)(b * 2001 + 1 + p) * DD + d4 * 4);
    int t = tidx[r];
    float4* dst = reinterpret_cast<float4*>(g_tour + (size_t)(b * TT + t) * DD + d4 * 4);
    atomicAdd(dst, v);
}

// ---------------- K2: tb = tour_emb @ W1b + b1 (fp16 MMA + LDSM) ----------------
#define TB_OFF_W (32 * 68)
#define TB_SMEM_U32 (TB_OFF_W + 128 * 68)
__global__ void __launch_bounds__(128, 5)
k_tb(const float* __restrict__ b1) {
    extern __shared__ unsigned su[];
    unsigned* As = su;
    unsigned* Ws = su + TB_OFF_W;
    int tid = threadIdx.x;
    int lane = tid & 31, wid = tid >> 5;
    int g = lane >> 2, t4 = lane & 3;
    int wr = wid & 1, wc = wid >> 1;
    int row0 = blockIdx.x * 32;

    for (int i = tid; i < 32 * 32; i += 128) {
        int r = i >> 5, c4 = i & 31;
        float4 v = *reinterpret_cast<const float4*>(g_tour + (size_t)(row0 + r) * DD + c4 * 4);
        As[r * 68 + 2 * c4]     = pack2(v.x, v.y);
        As[r * 68 + 2 * c4 + 1] = pack2(v.z, v.w);
    }
    for (int i = tid; i < 2048; i += 128) {
        int n = i >> 4, k4 = (i & 15) * 4;
        *reinterpret_cast<uint4*>(Ws + n * 68 + k4) =
            *reinterpret_cast<const uint4*>(g_Wbp + n * 64 + k4);
    }
    __syncthreads();

    uint32_t sbase = smem_u32(su);
    uint32_t aaddr = sbase + 4u * ((wr * 16 + (lane & 15)) * 68 + (lane >> 4) * 4);
    uint32_t baddr = sbase + 4u * (TB_OFF_W +
                     (wc * 64 + (lane & 7) + ((lane >= 16) ? 8 : 0)) * 68 +
                     ((lane & 8) ? 4 : 0));

    float acc[8][4];
#pragma unroll
    for (int j = 0; j < 8; j++)
#pragma unroll
        for (int i = 0; i < 4; i++) acc[j][i] = 0.f;

#pragma unroll
    for (int s = 0; s < 8; s++) {
        uint32_t a0, a1, a2, a3;
        LDSM4(a0, a1, a2, a3, aaddr + s * 32);
#pragma unroll
        for (int jp = 0; jp < 4; jp++) {
            uint32_t b0a, b1a, b0b, b1b;
            LDSM4(b0a, b1a, b0b, b1b, baddr + jp * (16 * 68 * 4) + s * 32);
            mma16816(acc[2 * jp],     a0, a1, a2, a3, b0a, b1a);
            mma16816(acc[2 * jp + 1], a0, a1, a2, a3, b0b, b1b);
        }
    }

    int r0 = wr * 16 + g, r1 = r0 + 8;
#pragma unroll
    for (int jt = 0; jt < 8; jt++) {
        int colb = wc * 64 + jt * 8 + 2 * t4;
        float2 bb = *reinterpret_cast<const float2*>(b1 + colb);
        *reinterpret_cast<float2*>(g_tb + (size_t)(row0 + r0) * DD + colb) =
            make_float2(acc[jt][0] + bb.x, acc[jt][1] + bb.y);
        *reinterpret_cast<float2*>(g_tb + (size_t)(row0 + r1) * DD + colb) =
            make_float2(acc[jt][2] + bb.x, acc[jt][3] + bb.y);
    }
}

// ---------------- K3: fused MLP, fp16 MMA + LDSM ----------------
// smem u32: Ah[64*68], H[64*68], W[128*68], ts[64]   (~70 KB -> 3 CTAs/SM)
// After phase2: Ad f32[64][132] aliases Ah+H; redc f32[2048] aliases W.
#define OFF_H  (64 * 68)
#define OFF_W  (2 * 64 * 68)
#define OFF_TS (2 * 64 * 68 + 128 * 68)
#define SMEM_U32 (OFF_TS + 64)

__global__ void __launch_bounds__(256, 3)
k_main(const float* __restrict__ emb, const int* __restrict__ tidx,
       const float* __restrict__ b2) {
    extern __shared__ unsigned su[];
    unsigned* Ah = su;
    unsigned* Hs = su + OFF_H;
    unsigned* Ws = su + OFF_W;
    int* ts = (int*)(su + OFF_TS);
    float* Ad   = (float*)su;             // [64][132] after phase2
    float* redc = (float*)(su + OFF_W);   // [2048]

    int tid = threadIdx.x;
    int lane = tid & 31, wid = tid >> 5;
    int g = lane >> 2, t4 = lane & 3;
    int wr = wid & 3, wc = wid >> 2;
    int b = blockIdx.y;
    int row0 = blockIdx.x * 64;
    int nrows = PP - row0; if (nrows > 64) nrows = 64;

    // ---- pack A tile (fp16) + load W1 + tour ids ----
    for (int i = tid; i < 64 * 32; i += 256) {
        int r = i >> 5, c4 = i & 31;
        float4 v = make_float4(0.f, 0.f, 0.f, 0.f);
        if (r < nrows)
            v = *reinterpret_cast<const float4*>(emb + (size_t)(b * 2001 + 1 + row0 + r) * DD + c4 * 4);
        Ah[r * 68 + 2 * c4]     = pack2(v.x, v.y);
        Ah[r * 68 + 2 * c4 + 1] = pack2(v.z, v.w);
    }
    for (int i = tid; i < 2048; i += 256) {
        int n = i >> 4, k4 = (i & 15) * 4;
        *reinterpret_cast<uint4*>(Ws + n * 68 + k4) =
            *reinterpret_cast<const uint4*>(g_W1p + n * 64 + k4);
    }
    if (tid < 64) {
        int t = 0;
        if (tid < nrows) t = tidx[b * PP + row0 + tid];
        ts[tid] = t;
    }
    __syncthreads();

    uint32_t sbase = smem_u32(su);
    // per-lane ldmatrix source addresses (A/H share the row pattern)
    uint32_t afrag_off = 4u * ((wr * 16 + (lane & 15)) * 68 + (lane >> 4) * 4);
    uint32_t aaddr = sbase + afrag_off;
    uint32_t haddr = sbase + 4u * OFF_H + afrag_off;
    uint32_t baddr = sbase + 4u * OFF_W +
                     4u * ((wc * 64 + (lane & 7) + ((lane >= 16) ? 8 : 0)) * 68 +
                           ((lane & 8) ? 4 : 0));

    float acc[8][4];
#pragma unroll
    for (int j = 0; j < 8; j++)
#pragma unroll
        for (int i = 0; i < 4; i++) acc[j][i] = 0.f;
    int r0 = wr * 16 + g, r1 = r0 + 8;

    // ---- phase 1: acc = A @ W1a ----
#pragma unroll
    for (int s = 0; s < 8; s++) {
        uint32_t a0, a1, a2, a3;
        LDSM4(a0, a1, a2, a3, aaddr + s * 32);
#pragma unroll
        for (int jp = 0; jp < 4; jp++) {
            uint32_t b0a, b1a, b0b, b1b;
            LDSM4(b0a, b1a, b0b, b1b, baddr + jp * (16 * 68 * 4) + s * 32);
            mma16816(acc[2 * jp],     a0, a1, a2, a3, b0a, b1a);
            mma16816(acc[2 * jp + 1], a0, a1, a2, a3, b0b, b1b);
        }
    }

    // ---- tb gather + relu -> H (fp16) ----
    {
        const float* tb0p = g_tb + (size_t)(b * TT + ts[r0]) * DD;
        const float* tb1p = g_tb + (size_t)(b * TT + ts[r1]) * DD;
#pragma unroll
        for (int jt = 0; jt < 8; jt++) {
            int colb = wc * 64 + jt * 8 + 2 * t4;
            int cp   = wc * 32 + jt * 4 + t4;
            float2 tb0 = *reinterpret_cast<const float2*>(tb0p + colb);
            float2 tb1 = *reinterpret_cast<const float2*>(tb1p + colb);
            Hs[r0 * 68 + cp] = pack2(fmaxf(acc[jt][0] + tb0.x, 0.f),
                                     fmaxf(acc[jt][1] + tb0.y, 0.f));
            Hs[r1 * 68 + cp] = pack2(fmaxf(acc[jt][2] + tb1.x, 0.f),
                                     fmaxf(acc[jt][3] + tb1.y, 0.f));
#pragma unroll
            for (int i = 0; i < 4; i++) acc[jt][i] = 0.f;
        }
    }
    __syncthreads();            // H complete; W1 reads done

    // ---- load W2, phase 2: acc = H @ W2 ----
    for (int i = tid; i < 2048; i += 256) {
        int n = i >> 4, k4 = (i & 15) * 4;
        *reinterpret_cast<uint4*>(Ws + n * 68 + k4) =
            *reinterpret_cast<const uint4*>(g_W2p + n * 64 + k4);
    }
    __syncthreads();
#pragma unroll
    for (int s = 0; s < 8; s++) {
        uint32_t a0, a1, a2, a3;
        LDSM4(a0, a1, a2, a3, haddr + s * 32);
#pragma unroll
        for (int jp = 0; jp < 4; jp++) {
            uint32_t b0a, b1a, b0b, b1b;
            LDSM4(b0a, b1a, b0b, b1b, baddr + jp * (16 * 68 * 4) + s * 32);
            mma16816(acc[2 * jp],     a0, a1, a2, a3, b0a, b1a);
            mma16816(acc[2 * jp + 1], a0, a1, a2, a3, b0b, b1b);
        }
    }
    __syncthreads();            // MMA smem reads done; Ah/Hs/Ws reusable

    // ---- epilogue: added = acc + b2 + cust (exact f32 re-read) -> Ad ----
    {
        int rr0 = row0 + r0; if (rr0 > PP - 1) rr0 = PP - 1;
        int rr1 = row0 + r1; if (rr1 > PP - 1) rr1 = PP - 1;
        const float* e0 = emb + (size_t)(b * 2001 + 1 + rr0) * DD;
        const float* e1 = emb + (size_t)(b * 2001 + 1 + rr1) * DD;
#pragma unroll
        for (int jt = 0; jt < 8; jt++) {
            int colb = wc * 64 + jt * 8 + 2 * t4;
            float2 bb = *reinterpret_cast<const float2*>(b2 + colb);
            float2 c0 = *reinterpret_cast<const float2*>(e0 + colb);
            float2 c1 = *reinterpret_cast<const float2*>(e1 + colb);
            *reinterpret_cast<float2*>(Ad + r0 * 132 + colb) =
                make_float2(acc[jt][0] + bb.x + c0.x, acc[jt][1] + bb.y + c0.y);
            *reinterpret_cast<float2*>(Ad + r1 * 132 + colb) =
                make_float2(acc[jt][2] + bb.x + c1.x, acc[jt][3] + bb.y + c1.y);
        }
    }
    __syncthreads();

    // ---- fused coalesced store + column sum/sumsq ----
    {
        int c4 = tid & 31;        // 16B chunk within row
        int rg = tid >> 5;        // row group (8 rows each)
        float s0 = 0.f, s1 = 0.f, s2 = 0.f, s3 = 0.f;
        float q0 = 0.f, q1 = 0.f, q2 = 0.f, q3 = 0.f;
#pragma unroll
        for (int m = 0; m < 8; m++) {
            int r = rg + m * 8;
            if (r < nrows) {
                float4 v = *reinterpret_cast<const float4*>(Ad + r * 132 + c4 * 4);
                *reinterpret_cast<float4*>(g_added + (size_t)(b * PP + row0 + r) * DD + c4 * 4) = v;
                s0 += v.x; s1 += v.y; s2 += v.z; s3 += v.w;
                q0 += v.x * v.x; q1 += v.y * v.y; q2 += v.z * v.z; q3 += v.w * v.w;
            }
        }
        __syncthreads();          // Ad reads done; redc (aliases Ws) writable
        float* rs = redc + rg * 128 + c4 * 4;
        rs[0] = s0; rs[1] = s1; rs[2] = s2; rs[3] = s3;
        float* rq = redc + 1024 + rg * 128 + c4 * 4;
        rq[0] = q0; rq[1] = q1; rq[2] = q2; rq[3] = q3;
        __syncthreads();
        if (tid < 128) {
            float s = 0.f;
#pragma unroll
            for (int m = 0; m < 8; m++) s += redc[m * 128 + tid];
            atomicAdd(&g_sum[b * DD + tid], s);
        } else {
            int col = tid - 128;
            float q = 0.f;
#pragma unroll
            for (int m = 0; m < 8; m++) q += redc[1024 + m * 128 + col];
            atomicAdd(&g_sumsq[b * DD + col], q);
        }
    }
}

// ---------------- K4: stats -> (scale, shift) ----------------
__global__ void k_stat(const float* __restrict__ gamma, const float* __restrict__ beta) {
    int i = blockIdx.x * blockDim.x + threadIdx.x;
    if (i >= BB * DD) return;
    int d = i & 127;
    float mean = g_sum[i] * (1.f / PP);
    float var  = g_sumsq[i] * (1.f / PP) - mean * mean;
    float sc = gamma[d] * rsqrtf(var + EPSL);
    float sh = beta[d] - mean * sc;
    g_sum[i] = sc;
    g_sumsq[i] = sh;
}

// ---------------- K5: normalize + depot copy ----------------
__global__ void k_norm(const float* __restrict__ emb, float* __restrict__ out) {
    int i = blockIdx.x * blockDim.x + threadIdx.x;
    const int N4 = BB * 2001 * 32;
    if (i >= N4) return;
    int d4 = i & 31;
    int row = i >> 5;
    int b = row / 2001;
    int pr = row - b * 2001;
    float4 o;
    if (pr == 0) {
        o = reinterpret_cast<const float4*>(emb)[i];
    } else {
        int p = pr - 1;
        float4 a = *reinterpret_cast<const float4*>(g_added + (size_t)(b * PP + p) * DD + d4 * 4);
        float4 s4 = *reinterpret_cast<const float4*>(g_sum + b * DD + d4 * 4);
        float4 h4 = *reinterpret_cast<const float4*>(g_sumsq + b * DD + d4 * 4);
        o.x = a.x * s4.x + h4.x;
        o.y = a.y * s4.y + h4.y;
        o.z = a.z * s4.z + h4.z;
        o.w = a.w * s4.w + h4.w;
    }
    reinterpret_cast<float4*>(out)[i] = o;
}

// ---------------- launch ----------------
extern "C" void kernel_launch(void* const* d_in, const int* in_sizes, int n_in,
                              void* d_out, int out_size) {
    int ti = -1;
    for (int i = 0; i < n_in; i++)
        if (in_sizes[i] == BB * PP) { ti = i; break; }
    const int*   tidx  = (const int*)  d_in[ti];
    const float* emb   = (const float*)d_in[ti + 1];
    const float* W1    = (const float*)d_in[ti + 2];
    const float* b1    = (const float*)d_in[ti + 3];
    const float* W2    = (const float*)d_in[ti + 4];
    const float* b2    = (const float*)d_in[ti + 5];
    const float* gamma = (const float*)d_in[ti + 6];
    const float* beta  = (const float*)d_in[ti + 7];
    float* out = (float*)d_out;

    const int SMEM_TB   = TB_SMEM_U32 * 4;   // ~43.5 KB
    const int SMEM_MAIN = SMEM_U32 * 4;      // ~70 KB
    cudaFuncSetAttribute(k_tb,   cudaFuncAttributeMaxDynamicSharedMemorySize, SMEM_TB);
    cudaFuncSetAttribute(k_main, cudaFuncAttributeMaxDynamicSharedMemorySize, SMEM_MAIN);

    k_init<<<(BB * TT * DD + 255) / 256, 256>>>(W1, W2);
    k_seg<<<(BB * PP * 32 + 255) / 256, 256>>>(emb, tidx);
    k_tb<<<(BB * TT) / 32, 128, SMEM_TB>>>(b1);
    k_main<<<dim3((PP + 63) / 64, BB), 256, SMEM_MAIN>>>(emb, tidx, b2);
    k_stat<<<(BB * DD + 255) / 256, 256>>>(gamma, beta);
    k_norm<<<(BB * 2001 * 32 + 255) / 256, 256>>>(emb, out);
}

// round 8
// speedup vs baseline: 1.0882x; 1.0882x over previous
#include <cuda_runtime.h>
#include <cuda_fp16.h>
#include <cstddef>
#include <cstdint>

#define BB 64
#define PP 2000
#define DD 128
#define TT 200
#define TILES 32
#define EPSL 1e-5f

// ---------------- scratch ----------------
__device__ float g_tour [BB * TT * DD];
__device__ float g_tb   [BB * TT * DD];
__device__ float g_sum  [BB * DD];
__device__ float g_sumsq[BB * DD];
__device__ int   g_cnt  [BB];
// fp16x2 packed weights: [n][kp], kp in [0,64), pair = (W[2kp][n], W[2kp+1][n])
__device__ unsigned g_W1p[DD * 64];   // W1 rows [0,128)
__device__ unsigned g_Wbp[DD * 64];   // W1 rows [128,256)
__device__ unsigned g_W2p[DD * 64];

static __device__ __forceinline__ unsigned pack2(float v0, float v1) {
    __half2 h = __floats2half2_rn(v0, v1);
    return *reinterpret_cast<unsigned*>(&h);
}

static __device__ __forceinline__ void mma16816(float* c, unsigned a0, unsigned a1,
                                                unsigned a2, unsigned a3,
                                                unsigned b0, unsigned b1) {
    asm volatile(
        "mma.sync.aligned.m16n8k16.row.col.f32.f16.f16.f32 "
        "{%0,%1,%2,%3}, {%4,%5,%6,%7}, {%8,%9}, {%0,%1,%2,%3};"
        : "+f"(c[0]), "+f"(c[1]), "+f"(c[2]), "+f"(c[3])
        : "r"(a0), "r"(a1), "r"(a2), "r"(a3), "r"(b0), "r"(b1));
}

// ---------------- K0: zero + pack weights ----------------
__global__ void k_init(const float* __restrict__ W1, const float* __restrict__ W2) {
    int i = blockIdx.x * blockDim.x + threadIdx.x;
    if (i < BB * TT * DD) g_tour[i] = 0.f;
    if (i < BB * DD) { g_sum[i] = 0.f; g_sumsq[i] = 0.f; }
    if (i < BB) g_cnt[i] = 0;
    if (i < 3 * DD * 64) {
        int m  = i >> 13;
        int n  = (i >> 6) & 127;
        int kp = i & 63;
        const float* W = (m == 0) ? W1 : (m == 1) ? (W1 + 128 * DD) : W2;
        unsigned p = pack2(W[(2 * kp) * DD + n], W[(2 * kp + 1) * DD + n]);
        if (m == 0)      g_W1p[n * 64 + kp] = p;
        else if (m == 1) g_Wbp[n * 64 + kp] = p;
        else             g_W2p[n * 64 + kp] = p;
    }
}

// ---------------- K1: segment sum ----------------
__global__ void k_seg(const float* __restrict__ emb, const int* __restrict__ tidx) {
    int i = blockIdx.x * blockDim.x + threadIdx.x;
    int d4 = i & 31;
    int r  = i >> 5;
    if (r >= BB * PP) return;
    int b = r / PP, p = r - b * PP;
    const float4 v = *reinterpret_cast<const float4*>(emb + (size_t)(b * 2001 + 1 + p) * DD + d4 * 4);
    int t = tidx[r];
    float4* dst = reinterpret_cast<float4*>(g_tour + (size_t)(b * TT + t) * DD + d4 * 4);
    atomicAdd(dst, v);
}

// ---------------- K2: tb = tour_emb @ W1b + b1 ----------------
#define TB_OFF_W (32 * 68)
#define TB_SMEM_U32 (TB_OFF_W + 128 * 68)
__global__ void __launch_bounds__(128, 5)
k_tb(const float* __restrict__ b1) {
    extern __shared__ unsigned su[];
    unsigned* As = su;
    unsigned* Ws = su + TB_OFF_W;
    int tid = threadIdx.x;
    int lane = tid & 31, wid = tid >> 5;
    int g = lane >> 2, t4 = lane & 3;
    int wr = wid & 1, wc = wid >> 1;
    int row0 = blockIdx.x * 32;

    for (int i = tid; i < 32 * 32; i += 128) {
        int r = i >> 5, c4 = i & 31;
        float4 v = *reinterpret_cast<const float4*>(g_tour + (size_t)(row0 + r) * DD + c4 * 4);
        As[r * 68 + 2 * c4]     = pack2(v.x, v.y);
        As[r * 68 + 2 * c4 + 1] = pack2(v.z, v.w);
    }
    for (int i = tid; i < 2048; i += 128) {
        int n = i >> 4, k4 = (i & 15) * 4;
        *reinterpret_cast<uint4*>(Ws + n * 68 + k4) =
            *reinterpret_cast<const uint4*>(g_Wbp + n * 64 + k4);
    }
    __syncthreads();

    float acc[8][4];
#pragma unroll
    for (int j = 0; j < 8; j++)
#pragma unroll
        for (int i = 0; i < 4; i++) acc[j][i] = 0.f;
    int r0 = wr * 16 + g, r1 = r0 + 8;

#pragma unroll
    for (int s = 0; s < 8; s++) {
        unsigned a0 = As[r0 * 68 + s * 8 + t4];
        unsigned a1 = As[r1 * 68 + s * 8 + t4];
        unsigned a2 = As[r0 * 68 + s * 8 + t4 + 4];
        unsigned a3 = As[r1 * 68 + s * 8 + t4 + 4];
#pragma unroll
        for (int jt = 0; jt < 8; jt++) {
            int n = wc * 64 + jt * 8 + g;
            mma16816(acc[jt], a0, a1, a2, a3,
                     Ws[n * 68 + s * 8 + t4], Ws[n * 68 + s * 8 + t4 + 4]);
        }
    }

#pragma unroll
    for (int jt = 0; jt < 8; jt++) {
        int colb = wc * 64 + jt * 8 + 2 * t4;
        float2 bb = *reinterpret_cast<const float2*>(b1 + colb);
        *reinterpret_cast<float2*>(g_tb + (size_t)(row0 + r0) * DD + colb) =
            make_float2(acc[jt][0] + bb.x, acc[jt][1] + bb.y);
        *reinterpret_cast<float2*>(g_tb + (size_t)(row0 + r1) * DD + colb) =
            make_float2(acc[jt][2] + bb.x, acc[jt][3] + bb.y);
    }
}

// ---------------- K3: fused MLP + residual + stats + spin + layernorm ----------------
// smem u32: Ah[64*68], H[64*68], W[128*68], ts[64]   (~70 KB -> 3 CTAs/SM)
// After phase2: Ad f32[64][132] aliases Ah+H; redc f32[2048] aliases W.
#define OFF_H  (64 * 68)
#define OFF_W  (2 * 64 * 68)
#define OFF_TS (2 * 64 * 68 + 128 * 68)
#define SMEM_U32 (OFF_TS + 64)

__global__ void __launch_bounds__(256, 3)
k_main(const float* __restrict__ emb, const int* __restrict__ tidx,
       const float* __restrict__ b2, const float* __restrict__ gamma,
       const float* __restrict__ beta, float* __restrict__ out) {
    extern __shared__ unsigned su[];
    unsigned* Ah = su;
    unsigned* Hs = su + OFF_H;
    unsigned* Ws = su + OFF_W;
    int* ts = (int*)(su + OFF_TS);
    float* Ad   = (float*)su;             // [64][132] after phase2
    float* redc = (float*)(su + OFF_W);   // [2048]

    int tid = threadIdx.x;
    int lane = tid & 31, wid = tid >> 5;
    int g = lane >> 2, t4 = lane & 3;
    int wr = wid & 3, wc = wid >> 2;
    int b = blockIdx.y;
    int row0 = blockIdx.x * 64;
    int nrows = PP - row0; if (nrows > 64) nrows = 64;

    // ---- depot row copy (tile 0 only, overlapped with everything) ----
    if (blockIdx.x == 0 && tid < 32) {
        reinterpret_cast<float4*>(out + (size_t)b * 2001 * DD)[tid] =
            reinterpret_cast<const float4*>(emb + (size_t)b * 2001 * DD)[tid];
    }

    // ---- pack A tile (fp16) + load W1 + tour ids ----
    for (int i = tid; i < 64 * 32; i += 256) {
        int r = i >> 5, c4 = i & 31;
        float4 v = make_float4(0.f, 0.f, 0.f, 0.f);
        if (r < nrows)
            v = *reinterpret_cast<const float4*>(emb + (size_t)(b * 2001 + 1 + row0 + r) * DD + c4 * 4);
        Ah[r * 68 + 2 * c4]     = pack2(v.x, v.y);
        Ah[r * 68 + 2 * c4 + 1] = pack2(v.z, v.w);
    }
    for (int i = tid; i < 2048; i += 256) {
        int n = i >> 4, k4 = (i & 15) * 4;
        *reinterpret_cast<uint4*>(Ws + n * 68 + k4) =
            *reinterpret_cast<const uint4*>(g_W1p + n * 64 + k4);
    }
    if (tid < 64) {
        int t = 0;
        if (tid < nrows) t = tidx[b * PP + row0 + tid];
        ts[tid] = t;
    }
    __syncthreads();

    float acc[8][4];
#pragma unroll
    for (int j = 0; j < 8; j++)
#pragma unroll
        for (int i = 0; i < 4; i++) acc[j][i] = 0.f;
    int r0 = wr * 16 + g, r1 = r0 + 8;

    // ---- phase 1: acc = A @ W1a ----
#pragma unroll
    for (int s = 0; s < 8; s++) {
        unsigned a0 = Ah[r0 * 68 + s * 8 + t4];
        unsigned a1 = Ah[r1 * 68 + s * 8 + t4];
        unsigned a2 = Ah[r0 * 68 + s * 8 + t4 + 4];
        unsigned a3 = Ah[r1 * 68 + s * 8 + t4 + 4];
#pragma unroll
        for (int jt = 0; jt < 8; jt++) {
            int n = wc * 64 + jt * 8 + g;
            mma16816(acc[jt], a0, a1, a2, a3,
                     Ws[n * 68 + s * 8 + t4], Ws[n * 68 + s * 8 + t4 + 4]);
        }
    }

    // ---- tb gather + relu -> H (fp16) ----
    {
        const float* tb0p = g_tb + (size_t)(b * TT + ts[r0]) * DD;
        const float* tb1p = g_tb + (size_t)(b * TT + ts[r1]) * DD;
#pragma unroll
        for (int jt = 0; jt < 8; jt++) {
            int colb = wc * 64 + jt * 8 + 2 * t4;
            int cp   = wc * 32 + jt * 4 + t4;
            float2 tb0 = *reinterpret_cast<const float2*>(tb0p + colb);
            float2 tb1 = *reinterpret_cast<const float2*>(tb1p + colb);
            Hs[r0 * 68 + cp] = pack2(fmaxf(acc[jt][0] + tb0.x, 0.f),
                                     fmaxf(acc[jt][1] + tb0.y, 0.f));
            Hs[r1 * 68 + cp] = pack2(fmaxf(acc[jt][2] + tb1.x, 0.f),
                                     fmaxf(acc[jt][3] + tb1.y, 0.f));
#pragma unroll
            for (int i = 0; i < 4; i++) acc[jt][i] = 0.f;
        }
    }
    __syncthreads();            // H complete; W1 reads done

    // ---- load W2, phase 2: acc = H @ W2 ----
    for (int i = tid; i < 2048; i += 256) {
        int n = i >> 4, k4 = (i & 15) * 4;
        *reinterpret_cast<uint4*>(Ws + n * 68 + k4) =
            *reinterpret_cast<const uint4*>(g_W2p + n * 64 + k4);
    }
    __syncthreads();
#pragma unroll
    for (int s = 0; s < 8; s++) {
        unsigned a0 = Hs[r0 * 68 + s * 8 + t4];
        unsigned a1 = Hs[r1 * 68 + s * 8 + t4];
        unsigned a2 = Hs[r0 * 68 + s * 8 + t4 + 4];
        unsigned a3 = Hs[r1 * 68 + s * 8 + t4 + 4];
#pragma unroll
        for (int jt = 0; jt < 8; jt++) {
            int n = wc * 64 + jt * 8 + g;
            mma16816(acc[jt], a0, a1, a2, a3,
                     Ws[n * 68 + s * 8 + t4], Ws[n * 68 + s * 8 + t4 + 4]);
        }
    }
    __syncthreads();            // MMA smem reads done; Ah/Hs/Ws reusable

    // ---- epilogue: added = acc + b2 + cust (exact f32 re-read) -> Ad ----
    {
        int rr0 = row0 + r0; if (rr0 > PP - 1) rr0 = PP - 1;
        int rr1 = row0 + r1; if (rr1 > PP - 1) rr1 = PP - 1;
        const float* e0 = emb + (size_t)(b * 2001 + 1 + rr0) * DD;
        const float* e1 = emb + (size_t)(b * 2001 + 1 + rr1) * DD;
#pragma unroll
        for (int jt = 0; jt < 8; jt++) {
            int colb = wc * 64 + jt * 8 + 2 * t4;
            float2 bb = *reinterpret_cast<const float2*>(b2 + colb);
            float2 c0 = *reinterpret_cast<const float2*>(e0 + colb);
            float2 c1 = *reinterpret_cast<const float2*>(e1 + colb);
            *reinterpret_cast<float2*>(Ad + r0 * 132 + colb) =
                make_float2(acc[jt][0] + bb.x + c0.x, acc[jt][1] + bb.y + c0.y);
            *reinterpret_cast<float2*>(Ad + r1 * 132 + colb) =
                make_float2(acc[jt][2] + bb.x + c1.x, acc[jt][3] + bb.y + c1.y);
        }
    }
    __syncthreads();

    // ---- column sum/sumsq over valid rows -> global atomics ----
    int c4 = tid & 31;        // 16B chunk within row
    int rg = tid >> 5;        // row group (8 rows each)
    {
        float s0 = 0.f, s1 = 0.f, s2 = 0.f, s3 = 0.f;
        float q0 = 0.f, q1 = 0.f, q2 = 0.f, q3 = 0.f;
#pragma unroll
        for (int m = 0; m < 8; m++) {
            int r = rg + m * 8;
            if (r < nrows) {
                float4 v = *reinterpret_cast<const float4*>(Ad + r * 132 + c4 * 4);
                s0 += v.x; s1 += v.y; s2 += v.z; s3 += v.w;
                q0 += v.x * v.x; q1 += v.y * v.y; q2 += v.z * v.z; q3 += v.w * v.w;
            }
        }
        float* rs = redc + rg * 128 + c4 * 4;
        rs[0] = s0; rs[1] = s1; rs[2] = s2; rs[3] = s3;
        float* rq = redc + 1024 + rg * 128 + c4 * 4;
        rq[0] = q0; rq[1] = q1; rq[2] = q2; rq[3] = q3;
        __syncthreads();
        if (tid < 128) {
            float s = 0.f;
#pragma unroll
            for (int m = 0; m < 8; m++) s += redc[m * 128 + tid];
            atomicAdd(&g_sum[b * DD + tid], s);
        } else {
            int col = tid - 128;
            float q = 0.f;
#pragma unroll
            for (int m = 0; m < 8; m++) q += redc[1024 + m * 128 + col];
            atomicAdd(&g_sumsq[b * DD + col], q);
        }
    }
    __syncthreads();

    // ---- publish arrival, spin until all tiles of batch b done ----
    if (tid == 0) {
        __threadfence();                       // sums visible before arrival
        atomicAdd(&g_cnt[b], 1);
        volatile int* cp = g_cnt + b;
        while (*cp < TILES) __nanosleep(200);
    }
    __syncthreads();
    __threadfence();                           // order counter read before stat reads

    // ---- per-column scale/shift from totals; normalize Ad -> out ----
    {
        float4 S = __ldcg(reinterpret_cast<const float4*>(g_sum   + b * DD + c4 * 4));
        float4 Q = __ldcg(reinterpret_cast<const float4*>(g_sumsq + b * DD + c4 * 4));
        float4 G = *reinterpret_cast<const float4*>(gamma + c4 * 4);
        float4 Bt = *reinterpret_cast<const float4*>(beta + c4 * 4);
        const float inv = 1.f / PP;
        float m0 = S.x * inv, m1 = S.y * inv, m2 = S.z * inv, m3 = S.w * inv;
        float sc0 = G.x * rsqrtf(Q.x * inv - m0 * m0 + EPSL);
        float sc1 = G.y * rsqrtf(Q.y * inv - m1 * m1 + EPSL);
        float sc2 = G.z * rsqrtf(Q.z * inv - m2 * m2 + EPSL);
        float sc3 = G.w * rsqrtf(Q.w * inv - m3 * m3 + EPSL);
        float sh0 = Bt.x - m0 * sc0, sh1 = Bt.y - m1 * sc1;
        float sh2 = Bt.z - m2 * sc2, sh3 = Bt.w - m3 * sc3;
#pragma unroll
        for (int m = 0; m < 8; m++) {
            int r = rg + m * 8;
            if (r < nrows) {
                float4 v = *reinterpret_cast<const float4*>(Ad + r * 132 + c4 * 4);
                float4 o;
                o.x = v.x * sc0 + sh0;
                o.y = v.y * sc1 + sh1;
                o.z = v.z * sc2 + sh2;
                o.w = v.w * sc3 + sh3;
                *reinterpret_cast<float4*>(out + (size_t)(b * 2001 + 1 + row0 + r) * DD + c4 * 4) = o;
            }
        }
    }
}

// ---------------- launch ----------------
extern "C" void kernel_launch(void* const* d_in, const int* in_sizes, int n_in,
                              void* d_out, int out_size) {
    int ti = -1;
    for (int i = 0; i < n_in; i++)
        if (in_sizes[i] == BB * PP) { ti = i; break; }
    const int*   tidx  = (const int*)  d_in[ti];
    const float* emb   = (const float*)d_in[ti + 1];
    const float* W1    = (const float*)d_in[ti + 2];
    const float* b1    = (const float*)d_in[ti + 3];
    const float* W2    = (const float*)d_in[ti + 4];
    const float* b2    = (const float*)d_in[ti + 5];
    const float* gamma = (const float*)d_in[ti + 6];
    const float* beta  = (const float*)d_in[ti + 7];
    float* out = (float*)d_out;

    const int SMEM_TB   = TB_SMEM_U32 * 4;   // ~43.5 KB
    const int SMEM_MAIN = SMEM_U32 * 4;      // ~70 KB
    cudaFuncSetAttribute(k_tb,   cudaFuncAttributeMaxDynamicSharedMemorySize, SMEM_TB);
    cudaFuncSetAttribute(k_main, cudaFuncAttributeMaxDynamicSharedMemorySize, SMEM_MAIN);

    k_init<<<(BB * TT * DD + 255) / 256, 256>>>(W1, W2);
    k_seg<<<(BB * PP * 32 + 255) / 256, 256>>>(emb, tidx);
    k_tb<<<(BB * TT) / 32, 128, SMEM_TB>>>(b1);
    k_main<<<dim3(TILES, BB), 256, SMEM_MAIN>>>(emb, tidx, b2, gamma, beta, out);
}